// round 14
// baseline (speedup 1.0000x reference)
#include <cuda_runtime.h>
#include <cuda_fp16.h>
#include <cstdint>

#define N_NODES 102400
#define MAX_E   3276800
#define LATDIM  128
#define SLOTS   96         // Poisson(32): P(deg > 96) ~ 1e-18 per node
#define OVF_CAP 8192

// ---------------------------------------------------------------------------
// Device scratch (allocation-free).
// ---------------------------------------------------------------------------
__device__ int     g_cursor[N_NODES];
__device__ int2    g_edge[(size_t)N_NODES * SLOTS];      // (col, f32 val bits)
__device__ __half2 g_hemb[(size_t)N_NODES * (LATDIM/2)]; // fp16 copy of embeds
__device__ int     g_ovf_count;
__device__ int4    g_ovf[OVF_CAP];                       // (row, col, val bits, 0)

// ---------------------------------------------------------------------------
// K1: f32 -> f16 convert, SIDE STREAM, concurrent with scatter.
// __ldcs keeps the 52MB streaming read from evicting scatter's hot L2 lines.
// ---------------------------------------------------------------------------
#define CONV_BLOCKS 296
__global__ void __launch_bounds__(256) k_convert(const float* __restrict__ embeds) {
    const int NCONV = N_NODES * LATDIM / 4;              // float4 groups
    const int i = blockIdx.x * blockDim.x + threadIdx.x;
    const int stride = CONV_BLOCKS * 256;

    int k = i;
    for (; k + stride < NCONV; k += 2 * stride) {
        float4 f0 = __ldcs(((const float4*)embeds) + k);
        float4 f1 = __ldcs(((const float4*)embeds) + k + stride);
        uint2 p0, p1;
        __half2 a0 = __floats2half2_rn(f0.x, f0.y);
        __half2 a1 = __floats2half2_rn(f0.z, f0.w);
        __half2 b0 = __floats2half2_rn(f1.x, f1.y);
        __half2 b1 = __floats2half2_rn(f1.z, f1.w);
        p0.x = *reinterpret_cast<uint32_t*>(&a0);
        p0.y = *reinterpret_cast<uint32_t*>(&a1);
        p1.x = *reinterpret_cast<uint32_t*>(&b0);
        p1.y = *reinterpret_cast<uint32_t*>(&b1);
        reinterpret_cast<uint2*>(g_hemb)[k]          = p0;
        reinterpret_cast<uint2*>(g_hemb)[k + stride] = p1;
    }
    for (; k < NCONV; k += stride) {
        float4 f = __ldcs(((const float4*)embeds) + k);
        __half2 h0 = __floats2half2_rn(f.x, f.y);
        __half2 h1 = __floats2half2_rn(f.z, f.w);
        uint2 packed;
        packed.x = *reinterpret_cast<uint32_t*>(&h0);
        packed.y = *reinterpret_cast<uint32_t*>(&h1);
        reinterpret_cast<uint2*>(g_hemb)[k] = packed;
    }
}

// ---------------------------------------------------------------------------
// K2: single-pass bucket scatter (unchanged from champion).
// ---------------------------------------------------------------------------
__global__ void k_scatter(const int*   __restrict__ rows,
                          const int*   __restrict__ cols,
                          const float* __restrict__ vals,
                          int E) {
    const int E4 = E >> 2;
    const int i = blockIdx.x * blockDim.x + threadIdx.x;
    const int stride = gridDim.x * blockDim.x;

    for (int k = i; k < E4; k += stride) {
        int4   r = __ldg(((const int4*)  rows) + k);
        int4   c = __ldg(((const int4*)  cols) + k);
        float4 v = __ldg(((const float4*)vals) + k);
        int p0 = atomicAdd(&g_cursor[r.x], 1);
        int p1 = atomicAdd(&g_cursor[r.y], 1);
        int p2 = atomicAdd(&g_cursor[r.z], 1);
        int p3 = atomicAdd(&g_cursor[r.w], 1);

        #define EMIT(rr, pp, cc, vv)                                          \
            if (pp < SLOTS) {                                                 \
                g_edge[(size_t)(rr) * SLOTS + (pp)] =                         \
                    make_int2((cc), __float_as_int(vv));                      \
            } else {                                                          \
                int q = atomicAdd(&g_ovf_count, 1);                           \
                if (q < OVF_CAP)                                              \
                    g_ovf[q] = make_int4((rr), (cc), __float_as_int(vv), 0);  \
            }
        EMIT(r.x, p0, c.x, v.x)
        EMIT(r.y, p1, c.y, v.y)
        EMIT(r.z, p2, c.z, v.z)
        EMIT(r.w, p3, c.w, v.w)
    }
    for (int e = (E4 << 2) + i; e < E; e += stride) {
        int rr = rows[e];
        int p = atomicAdd(&g_cursor[rr], 1);
        EMIT(rr, p, cols[e], vals[e])
    }
    #undef EMIT
}

// ---------------------------------------------------------------------------
// K3: warp-per-node aggregation — R12 champion structure (fp32 chains, LDS
// broadcast, 32 regs / 81% occ), with the edge-record broadcast upgraded to
// LDS.128: one shared load feeds TWO edges (0.5 LDS/edge instead of 1).
// ---------------------------------------------------------------------------
__global__ void __launch_bounds__(256) k_agg(float* __restrict__ out) {
    __shared__ int4 s_ev4[8][16];                // [warp][2-edge pairs], 16B aligned
    const int wid  = threadIdx.x >> 5;
    const int node = (blockIdx.x * blockDim.x + threadIdx.x) >> 5;
    const int lane = threadIdx.x & 31;
    if (node >= N_NODES) return;

    const int raw_cnt = g_cursor[node];
    const int cnt = (raw_cnt > SLOTS) ? SLOTS : raw_cnt;
    const int2* bucket = g_edge + (size_t)node * SLOTS;

    float4 acc = make_float4(0.f, 0.f, 0.f, 0.f);

    int base = 0;
    for (; base + 32 <= cnt; base += 32) {
        int2 ev = __ldg(bucket + base + lane);
        __syncwarp();
        ((int2*)s_ev4[wid])[lane] = ev;
        __syncwarp();

        #pragma unroll 4
        for (int p = 0; p < 16; p++) {
            int4 e2 = s_ev4[wid][p];             // LDS.128 broadcast: 2 edges
            {
                float v = __int_as_float(e2.y);
                uint2 h = __ldg(reinterpret_cast<const uint2*>(
                              g_hemb + (size_t)e2.x * (LATDIM / 2)) + lane);
                __half2 h0 = *reinterpret_cast<__half2*>(&h.x);
                __half2 h1 = *reinterpret_cast<__half2*>(&h.y);
                float2 f0 = __half22float2(h0);
                float2 f1 = __half22float2(h1);
                acc.x = fmaf(v, f0.x, acc.x);
                acc.y = fmaf(v, f0.y, acc.y);
                acc.z = fmaf(v, f1.x, acc.z);
                acc.w = fmaf(v, f1.y, acc.w);
            }
            {
                float v = __int_as_float(e2.w);
                uint2 h = __ldg(reinterpret_cast<const uint2*>(
                              g_hemb + (size_t)e2.z * (LATDIM / 2)) + lane);
                __half2 h0 = *reinterpret_cast<__half2*>(&h.x);
                __half2 h1 = *reinterpret_cast<__half2*>(&h.y);
                float2 f0 = __half22float2(h0);
                float2 f1 = __half22float2(h1);
                acc.x = fmaf(v, f0.x, acc.x);
                acc.y = fmaf(v, f0.y, acc.y);
                acc.z = fmaf(v, f1.x, acc.z);
                acc.w = fmaf(v, f1.y, acc.w);
            }
        }
    }
    {
        const int n = cnt - base;
        if (n > 0) {
            int2 ev = (lane < n) ? __ldg(bucket + base + lane) : make_int2(0, 0);
            __syncwarp();
            ((int2*)s_ev4[wid])[lane] = ev;
            __syncwarp();
            for (int j = 0; j < n; j++) {
                int2  e = ((int2*)s_ev4[wid])[j];
                float v = __int_as_float(e.y);
                uint2 h = __ldg(reinterpret_cast<const uint2*>(
                              g_hemb + (size_t)e.x * (LATDIM / 2)) + lane);
                __half2 h0 = *reinterpret_cast<__half2*>(&h.x);
                __half2 h1 = *reinterpret_cast<__half2*>(&h.y);
                float2 f0 = __half22float2(h0);
                float2 f1 = __half22float2(h1);
                acc.x = fmaf(v, f0.x, acc.x);
                acc.y = fmaf(v, f0.y, acc.y);
                acc.z = fmaf(v, f1.x, acc.z);
                acc.w = fmaf(v, f1.y, acc.w);
            }
        }
    }

    // Overflow safety net (dead for this dataset; correctness guarantee).
    if (raw_cnt > SLOTS) {
        int ocnt = g_ovf_count;
        if (ocnt > OVF_CAP) ocnt = OVF_CAP;
        for (int e = 0; e < ocnt; e++) {
            int4 t = g_ovf[e];
            if (t.x == node) {
                float v = __int_as_float(t.z);
                uint2 h = __ldg(reinterpret_cast<const uint2*>(
                              g_hemb + (size_t)t.y * (LATDIM / 2)) + lane);
                __half2 h0 = *reinterpret_cast<__half2*>(&h.x);
                __half2 h1 = *reinterpret_cast<__half2*>(&h.y);
                float2 f0 = __half22float2(h0);
                float2 f1 = __half22float2(h1);
                acc.x = fmaf(v, f0.x, acc.x);
                acc.y = fmaf(v, f0.y, acc.y);
                acc.z = fmaf(v, f1.x, acc.z);
                acc.w = fmaf(v, f1.y, acc.w);
            }
        }
    }

    *reinterpret_cast<float4*>(out + (size_t)node * LATDIM + lane * 4) = acc;
}

// ---------------------------------------------------------------------------
// kernel_launch — fork/join: convert on a side stream concurrent with
// memset(cursors)+scatter on the main stream; join before agg.
// The cursor zeroing is a cudaMemsetAsync node (graph-capturable) instead of
// a kernel launch: saves the k_zero launch overhead (~4 us measured).
// ---------------------------------------------------------------------------
extern "C" void kernel_launch(void* const* d_in, const int* in_sizes, int n_in,
                              void* d_out, int out_size)
{
    int E = in_sizes[0] / 2;
    if (E > MAX_E) E = MAX_E;

    const int*   idx    = (const int*)  d_in[0];
    const float* vals   = (const float*)d_in[1];
    const float* embeds = (const float*)d_in[2];
    float*       out    = (float*)      d_out;

    const int* rows = idx;
    const int* cols = idx + E;

    void* p_cursor = nullptr;
    void* p_ovfcnt = nullptr;
    cudaGetSymbolAddress(&p_cursor, g_cursor);
    cudaGetSymbolAddress(&p_ovfcnt, g_ovf_count);

    cudaStream_t s2;
    cudaEvent_t  e_fork, e_join;
    cudaStreamCreateWithFlags(&s2, cudaStreamNonBlocking);
    cudaEventCreateWithFlags(&e_fork, cudaEventDisableTiming);
    cudaEventCreateWithFlags(&e_join, cudaEventDisableTiming);

    cudaEventRecord(e_fork, 0);
    cudaStreamWaitEvent(s2, e_fork, 0);

    k_convert<<<CONV_BLOCKS, 256, 0, s2>>>(embeds);

    cudaMemsetAsync(p_cursor, 0, N_NODES * sizeof(int), 0);
    cudaMemsetAsync(p_ovfcnt, 0, sizeof(int), 0);
    k_scatter<<<148 * 16, 256>>>(rows, cols, vals, E);

    cudaEventRecord(e_join, s2);
    cudaStreamWaitEvent(0, e_join, 0);

    k_agg<<<N_NODES / 8, 256>>>(out);
}

// round 15
// speedup vs baseline: 1.4036x; 1.4036x over previous
#include <cuda_runtime.h>
#include <cuda_fp16.h>
#include <cstdint>

#define N_NODES 102400
#define MAX_E   3276800
#define LATDIM  128
#define SLOTS   96         // Poisson(32): P(deg > 96) ~ 1e-18 per node
#define OVF_CAP 8192

// ---------------------------------------------------------------------------
// Device scratch (allocation-free).
// ---------------------------------------------------------------------------
__device__ int     g_cursor[N_NODES];
__device__ int2    g_edge[(size_t)N_NODES * SLOTS];      // (col, f32 val bits)
__device__ __half2 g_hemb[(size_t)N_NODES * (LATDIM/2)]; // fp16 copy of embeds
__device__ int     g_ovf_count;
__device__ int4    g_ovf[OVF_CAP];                       // (row, col, val bits, 0)

// ---------------------------------------------------------------------------
// K0: zero cursors + overflow counter (kernel — R14 showed memset nodes
// disturb the fork/join overlap).
// ---------------------------------------------------------------------------
__global__ void k_zero() {
    const int i = blockIdx.x * blockDim.x + threadIdx.x;
    if (i < N_NODES / 4) ((int4*)g_cursor)[i] = make_int4(0, 0, 0, 0);
    if (i == 0) g_ovf_count = 0;
}

// ---------------------------------------------------------------------------
// K1: f32 -> f16 convert, SIDE STREAM, concurrent with scatter.
// __ldcs keeps the 52MB streaming read from evicting scatter's hot L2 lines.
// ---------------------------------------------------------------------------
#define CONV_BLOCKS 296
__global__ void __launch_bounds__(256) k_convert(const float* __restrict__ embeds) {
    const int NCONV = N_NODES * LATDIM / 4;              // float4 groups
    const int i = blockIdx.x * blockDim.x + threadIdx.x;
    const int stride = CONV_BLOCKS * 256;

    int k = i;
    for (; k + stride < NCONV; k += 2 * stride) {
        float4 f0 = __ldcs(((const float4*)embeds) + k);
        float4 f1 = __ldcs(((const float4*)embeds) + k + stride);
        uint2 p0, p1;
        __half2 a0 = __floats2half2_rn(f0.x, f0.y);
        __half2 a1 = __floats2half2_rn(f0.z, f0.w);
        __half2 b0 = __floats2half2_rn(f1.x, f1.y);
        __half2 b1 = __floats2half2_rn(f1.z, f1.w);
        p0.x = *reinterpret_cast<uint32_t*>(&a0);
        p0.y = *reinterpret_cast<uint32_t*>(&a1);
        p1.x = *reinterpret_cast<uint32_t*>(&b0);
        p1.y = *reinterpret_cast<uint32_t*>(&b1);
        reinterpret_cast<uint2*>(g_hemb)[k]          = p0;
        reinterpret_cast<uint2*>(g_hemb)[k + stride] = p1;
    }
    for (; k < NCONV; k += stride) {
        float4 f = __ldcs(((const float4*)embeds) + k);
        __half2 h0 = __floats2half2_rn(f.x, f.y);
        __half2 h1 = __floats2half2_rn(f.z, f.w);
        uint2 packed;
        packed.x = *reinterpret_cast<uint32_t*>(&h0);
        packed.y = *reinterpret_cast<uint32_t*>(&h1);
        reinterpret_cast<uint2*>(g_hemb)[k] = packed;
    }
}

// ---------------------------------------------------------------------------
// K2: single-pass bucket scatter (unchanged from champion).
// ---------------------------------------------------------------------------
__global__ void k_scatter(const int*   __restrict__ rows,
                          const int*   __restrict__ cols,
                          const float* __restrict__ vals,
                          int E) {
    const int E4 = E >> 2;
    const int i = blockIdx.x * blockDim.x + threadIdx.x;
    const int stride = gridDim.x * blockDim.x;

    for (int k = i; k < E4; k += stride) {
        int4   r = __ldg(((const int4*)  rows) + k);
        int4   c = __ldg(((const int4*)  cols) + k);
        float4 v = __ldg(((const float4*)vals) + k);
        int p0 = atomicAdd(&g_cursor[r.x], 1);
        int p1 = atomicAdd(&g_cursor[r.y], 1);
        int p2 = atomicAdd(&g_cursor[r.z], 1);
        int p3 = atomicAdd(&g_cursor[r.w], 1);

        #define EMIT(rr, pp, cc, vv)                                          \
            if (pp < SLOTS) {                                                 \
                g_edge[(size_t)(rr) * SLOTS + (pp)] =                         \
                    make_int2((cc), __float_as_int(vv));                      \
            } else {                                                          \
                int q = atomicAdd(&g_ovf_count, 1);                           \
                if (q < OVF_CAP)                                              \
                    g_ovf[q] = make_int4((rr), (cc), __float_as_int(vv), 0);  \
            }
        EMIT(r.x, p0, c.x, v.x)
        EMIT(r.y, p1, c.y, v.y)
        EMIT(r.z, p2, c.z, v.z)
        EMIT(r.w, p3, c.w, v.w)
    }
    for (int e = (E4 << 2) + i; e < E; e += stride) {
        int rr = rows[e];
        int p = atomicAdd(&g_cursor[rr], 1);
        EMIT(rr, p, cols[e], vals[e])
    }
    #undef EMIT
}

// ---------------------------------------------------------------------------
// K3: warp-per-node aggregation — exact R12 champion structure (fp32 chains,
// LDS.64 broadcast, unroll 8), with ONE change: 32-bit byte-offset gather
// addressing (g_hemb is 26MB so (col << 8) fits 32 bits) replacing the
// per-edge IMAD.WIDE 64-bit chain.
// ---------------------------------------------------------------------------
__global__ void __launch_bounds__(256) k_agg(float* __restrict__ out) {
    __shared__ int2 s_ev[8][32];                 // [warp][edge-in-chunk]
    const int wid  = threadIdx.x >> 5;
    const int node = (blockIdx.x * blockDim.x + threadIdx.x) >> 5;
    const int lane = threadIdx.x & 31;
    if (node >= N_NODES) return;

    const int raw_cnt = g_cursor[node];
    const int cnt = (raw_cnt > SLOTS) ? SLOTS : raw_cnt;
    const int2* bucket = g_edge + (size_t)node * SLOTS;
    const char* hbase = (const char*)g_hemb + lane * 8;   // lane's 8B slice

    float4 acc = make_float4(0.f, 0.f, 0.f, 0.f);

    int base = 0;
    for (; base + 32 <= cnt; base += 32) {
        int2 ev = __ldg(bucket + base + lane);
        __syncwarp();
        s_ev[wid][lane] = ev;
        __syncwarp();

        #pragma unroll 8
        for (int j = 0; j < 32; j++) {
            int2  e = s_ev[wid][j];              // LDS.64 broadcast (N=1)
            float v = __int_as_float(e.y);
            uint2 h = __ldg((const uint2*)(hbase + ((unsigned)e.x << 8)));
            __half2 h0 = *reinterpret_cast<__half2*>(&h.x);
            __half2 h1 = *reinterpret_cast<__half2*>(&h.y);
            float2 f0 = __half22float2(h0);
            float2 f1 = __half22float2(h1);
            acc.x = fmaf(v, f0.x, acc.x);
            acc.y = fmaf(v, f0.y, acc.y);
            acc.z = fmaf(v, f1.x, acc.z);
            acc.w = fmaf(v, f1.y, acc.w);
        }
    }
    {
        const int n = cnt - base;
        if (n > 0) {
            int2 ev = (lane < n) ? __ldg(bucket + base + lane) : make_int2(0, 0);
            __syncwarp();
            s_ev[wid][lane] = ev;
            __syncwarp();
            for (int j = 0; j < n; j++) {
                int2  e = s_ev[wid][j];
                float v = __int_as_float(e.y);
                uint2 h = __ldg((const uint2*)(hbase + ((unsigned)e.x << 8)));
                __half2 h0 = *reinterpret_cast<__half2*>(&h.x);
                __half2 h1 = *reinterpret_cast<__half2*>(&h.y);
                float2 f0 = __half22float2(h0);
                float2 f1 = __half22float2(h1);
                acc.x = fmaf(v, f0.x, acc.x);
                acc.y = fmaf(v, f0.y, acc.y);
                acc.z = fmaf(v, f1.x, acc.z);
                acc.w = fmaf(v, f1.y, acc.w);
            }
        }
    }

    // Overflow safety net (dead for this dataset; correctness guarantee).
    if (raw_cnt > SLOTS) {
        int ocnt = g_ovf_count;
        if (ocnt > OVF_CAP) ocnt = OVF_CAP;
        for (int e = 0; e < ocnt; e++) {
            int4 t = g_ovf[e];
            if (t.x == node) {
                float v = __int_as_float(t.z);
                uint2 h = __ldg((const uint2*)(hbase + ((unsigned)t.y << 8)));
                __half2 h0 = *reinterpret_cast<__half2*>(&h.x);
                __half2 h1 = *reinterpret_cast<__half2*>(&h.y);
                float2 f0 = __half22float2(h0);
                float2 f1 = __half22float2(h1);
                acc.x = fmaf(v, f0.x, acc.x);
                acc.y = fmaf(v, f0.y, acc.y);
                acc.z = fmaf(v, f1.x, acc.z);
                acc.w = fmaf(v, f1.y, acc.w);
            }
        }
    }

    *reinterpret_cast<float4*>(out + (size_t)node * LATDIM + lane * 4) = acc;
}

// ---------------------------------------------------------------------------
// kernel_launch — fork/join: convert on a side stream concurrent with
// zero+scatter on the main stream; join before agg. (Exact R12 topology.)
// ---------------------------------------------------------------------------
extern "C" void kernel_launch(void* const* d_in, const int* in_sizes, int n_in,
                              void* d_out, int out_size)
{
    int E = in_sizes[0] / 2;
    if (E > MAX_E) E = MAX_E;

    const int*   idx    = (const int*)  d_in[0];
    const float* vals   = (const float*)d_in[1];
    const float* embeds = (const float*)d_in[2];
    float*       out    = (float*)      d_out;

    const int* rows = idx;
    const int* cols = idx + E;

    cudaStream_t s2;
    cudaEvent_t  e_fork, e_join;
    cudaStreamCreateWithFlags(&s2, cudaStreamNonBlocking);
    cudaEventCreateWithFlags(&e_fork, cudaEventDisableTiming);
    cudaEventCreateWithFlags(&e_join, cudaEventDisableTiming);

    cudaEventRecord(e_fork, 0);
    cudaStreamWaitEvent(s2, e_fork, 0);

    k_convert<<<CONV_BLOCKS, 256, 0, s2>>>(embeds);

    k_zero<<<(N_NODES / 4 + 255) / 256, 256>>>();
    k_scatter<<<148 * 16, 256>>>(rows, cols, vals, E);

    cudaEventRecord(e_join, s2);
    cudaStreamWaitEvent(0, e_join, 0);

    k_agg<<<N_NODES / 8, 256>>>(out);
}